// round 11
// baseline (speedup 1.0000x reference)
#include <cuda_runtime.h>
#include <math.h>
#include <stdint.h>

#define BH 64
#define QL 512
#define KL 4096
#define DD 128
#define RR 32
#define NCH 8
#define CHUNK 512          // KL / NCH
#define MAXSWEEP 8
#define PITCH 129          // smem pitch for 128x128 matrices

typedef unsigned long long u64;

// ---------------- packed f32x2 helpers (sm_103a) ----------------
__device__ __forceinline__ u64 pk2(float x, float y) {
    u64 r; asm("mov.b64 %0,{%1,%2};" : "=l"(r) : "f"(x), "f"(y)); return r;
}
__device__ __forceinline__ void up2(u64 v, float& lo, float& hi) {
    asm("mov.b64 {%0,%1},%2;" : "=f"(lo), "=f"(hi) : "l"(v));
}
__device__ __forceinline__ u64 fma2(u64 a, u64 b, u64 c) {
    u64 d; asm("fma.rn.f32x2 %0,%1,%2,%3;" : "=l"(d) : "l"(a), "l"(b), "l"(c)); return d;
}
__device__ __forceinline__ u64 mul2(u64 a, u64 b) {
    u64 d; asm("mul.rn.f32x2 %0,%1,%2;" : "=l"(d) : "l"(a), "l"(b)); return d;
}

// ---------------- device scratch (static allocation only) ----------------
__device__ float g_Gpart[BH*NCH*DD*DD];   // partial Gram matrices
__device__ float g_mspart[BH*NCH*DD];     // partial column sums
__device__ float g_B[BH*DD*RR];           // top-32 eigenbasis  [bh][d][r]
__device__ float g_Kp[(size_t)BH*KL*RR];  // K projected
__device__ float g_Qp[(size_t)BH*QL*RR];  // Q projected (pre-scaled)

// ---------------- cluster / mbarrier helpers ----------------
__device__ __forceinline__ uint32_t s2u(const void* p) {
    uint32_t a;
    asm("{ .reg .u64 t; cvta.to.shared.u64 t, %1; cvt.u32.u64 %0, t; }"
        : "=r"(a) : "l"(p));
    return a;
}
__device__ __forceinline__ uint32_t ctarank() {
    uint32_t r; asm("mov.u32 %0, %%cluster_ctarank;" : "=r"(r)); return r;
}
__device__ __forceinline__ uint32_t mapa_u32(uint32_t a, uint32_t r) {
    uint32_t o; asm("mapa.shared::cluster.u32 %0, %1, %2;" : "=r"(o) : "r"(a), "r"(r));
    return o;
}
__device__ __forceinline__ void mbar_init(uint32_t a, uint32_t cnt) {
    asm volatile("mbarrier.init.shared.b64 [%0], %1;" :: "r"(a), "r"(cnt) : "memory");
}
__device__ __forceinline__ void mbar_arrive_remote(uint32_t ra) {
    asm volatile("mbarrier.arrive.release.cluster.shared::cluster.b64 _, [%0];"
                 :: "r"(ra) : "memory");
}
__device__ __forceinline__ void dsmem_st_v2f(uint32_t ra, float x, float y) {
    asm volatile("st.shared::cluster.v2.f32 [%0], {%1,%2};"
                 :: "r"(ra), "f"(x), "f"(y) : "memory");
}
__device__ __forceinline__ void dsmem_st_b32(uint32_t ra, uint32_t v) {
    asm volatile("st.shared::cluster.b32 [%0], %1;" :: "r"(ra), "r"(v) : "memory");
}
// blocking parity wait, cluster-scope acquire
__device__ __forceinline__ void mbar_wait(uint32_t a, uint32_t parity) {
    uint32_t done;
    asm volatile(
        "{\n\t.reg .pred p;\n\t"
        "mbarrier.try_wait.parity.acquire.cluster.shared::cta.b64 p, [%1], %2;\n\t"
        "selp.b32 %0, 1, 0, p;\n\t}"
        : "=r"(done) : "r"(a), "r"(parity) : "memory");
    if (!done) {
        asm volatile(
            "{\n\t.reg .pred P1;\n\t"
            "WL_%=:\n\t"
            "mbarrier.try_wait.parity.acquire.cluster.shared::cta.b64 P1, [%0], %1, 0x989680;\n\t"
            "@P1 bra.uni WD_%=;\n\t"
            "bra.uni WL_%=;\n\t"
            "WD_%=:\n\t}"
            :: "r"(a), "r"(parity) : "memory");
    }
}
#define CLUSTER_SYNC() do { \
    asm volatile("barrier.cluster.arrive.aligned;" ::: "memory"); \
    asm volatile("barrier.cluster.wait.aligned;"   ::: "memory"); \
} while (0)

// =========================================================================
// Kernel 1: partial Gram  G_chunk = K_chunk^T K_chunk   + column sums
// grid (64, 8), 256 threads.  8x8 register tile, f32x2 accumulation.
// =========================================================================
__global__ void gram_partial_kernel(const float* __restrict__ K)
{
    const int bh = blockIdx.x, ch = blockIdx.y;
    const float* Kb = K + ((size_t)bh*KL + (size_t)ch*CHUNK)*DD;

    __shared__ __align__(16) float Ks[16][DD];

    const int tid = threadIdx.x;
    const int ti = tid >> 4, tj = tid & 15;
    u64 acc2[8][4];
#pragma unroll
    for (int i = 0; i < 8; i++)
#pragma unroll
        for (int j = 0; j < 4; j++) acc2[i][j] = 0ull;
    float cs = 0.f;

    for (int n0 = 0; n0 < CHUNK; n0 += 16) {
        const float4* src = (const float4*)(Kb + (size_t)n0*DD);
        float4* dst = (float4*)(&Ks[0][0]);
#pragma unroll
        for (int i = tid; i < 16*DD/4; i += 256) dst[i] = src[i];
        __syncthreads();

        for (int n = 0; n < 16; n++) {
            float a[8];
            *(float4*)&a[0] = *(float4*)&Ks[n][ti*8];
            *(float4*)&a[4] = *(float4*)&Ks[n][ti*8+4];
            u64 b2[4];
            const ulonglong2* bp = (const ulonglong2*)&Ks[n][tj*8];
            ulonglong2 t0 = bp[0], t1 = bp[1];
            b2[0] = t0.x; b2[1] = t0.y; b2[2] = t1.x; b2[3] = t1.y;
#pragma unroll
            for (int i = 0; i < 8; i++) {
                const u64 a2 = pk2(a[i], a[i]);
#pragma unroll
                for (int j = 0; j < 4; j++) acc2[i][j] = fma2(a2, b2[j], acc2[i][j]);
            }
        }
        if (tid < DD) {
#pragma unroll
            for (int n = 0; n < 16; n++) cs += Ks[n][tid];
        }
        __syncthreads();
    }

    float* Gp = g_Gpart + ((size_t)(bh*NCH + ch))*DD*DD;
#pragma unroll
    for (int i = 0; i < 8; i++) {
        ulonglong2* op = (ulonglong2*)&Gp[(ti*8+i)*DD + tj*8];
        ulonglong2 o0, o1;
        o0.x = acc2[i][0]; o0.y = acc2[i][1];
        o1.x = acc2[i][2]; o1.y = acc2[i][3];
        op[0] = o0; op[1] = o1;
    }
    if (tid < DD) g_mspart[(bh*NCH + ch)*DD + tid] = cs;
}

// =========================================================================
// Kernel 2: cluster-split Jacobi. 2 CTAs per bh (rank0: A; rank1: V).
// Coefficients rank0 -> rank1 via 4-slot dsmem ring + mbarriers.
// rank1 V-update: 16 threads per rotation pair (pairing computed once).
// grid 128 (cluster 2), 1024 threads, 66048 B dynamic smem per CTA.
// =========================================================================
__global__ void __launch_bounds__(1024, 1) __cluster_dims__(2, 1, 1)
jacobi_cluster_kernel()
{
    extern __shared__ float sm[];     // rank0: A[128][129]; rank1: Vm[128][129]

    __shared__ float cbuf[4][132];    // slot: 64x(c,s) interleaved, [128]=flag
    __shared__ __align__(8) unsigned long long mbar[8];  // [0..3]=empty, [4..7]=full
    __shared__ float ssum[DD];
    __shared__ int   pr_[64], qr_[64];
    __shared__ float rc_[64], rs_[64];
    __shared__ float red_o[32], red_d[32];
    __shared__ float ev[DD];
    __shared__ int   rank_[DD];
    __shared__ int   s_done;

    const int bh  = blockIdx.x >> 1;
    const int tid = threadIdx.x;
    const int lane = tid & 31, wid = tid >> 5;
    const uint32_t rk = ctarank();

    const uint32_t cbuf_u  = s2u(&cbuf[0][0]);
    const uint32_t empty_u = s2u(&mbar[0]);
    const uint32_t full_u  = s2u(&mbar[4]);

    if (tid == 0) {
        if (rk == 0) { for (int i = 0; i < 4; i++) mbar_init(empty_u + i*8, 1); }
        else         { for (int i = 0; i < 4; i++) mbar_init(full_u  + i*8, 64); }
    }
    __syncthreads();
    CLUSTER_SYNC();

    if (rk == 0) {
        // =============== rank 0: A-side ===============
        float* A = sm;

        if (tid < DD) {
            float t = 0.f;
#pragma unroll
            for (int c = 0; c < NCH; c++) t += g_mspart[(bh*NCH + c)*DD + tid];
            ssum[tid] = t;
        }
        __syncthreads();
        const float invn = 1.f/(float)KL;
        for (int e = tid; e < DD*DD; e += 1024) {
            const int i = e >> 7, j = e & 127;
            float t = 0.f;
#pragma unroll
            for (int c = 0; c < NCH; c++) t += g_Gpart[((size_t)(bh*NCH + c) << 14) + e];
            A[i*PITCH + j] = t - ssum[i]*ssum[j]*invn;
        }
        __syncthreads();

        int iter = 0, tmod = 0, done = 0;
        for (int sweep = 0; sweep < MAXSWEEP && !done; sweep++) {
            for (int step = 0; step < 127; step++) {
                const int s = iter & 3;

                if (tid < 64) {
                    if (iter >= 4)
                        mbar_wait(empty_u + s*8, (uint32_t)((((iter >> 2)) ^ 1) & 1));

                    int p;
                    if (tid == 0) p = 0;
                    else { int r = tid - 1 - tmod; if (r < 0) r += 127; p = 1 + r; }
                    int r2 = 126 - tid - tmod; if (r2 < 0) r2 += 127;
                    const int q = 1 + r2;

                    const float app = A[p*PITCH + p];
                    const float aqq = A[q*PITCH + q];
                    const float apq = A[p*PITCH + q];
                    float c = 1.f, sv = 0.f;
                    if (fabsf(apq) > 1e-10f*(fabsf(app) + fabsf(aqq)) + 1e-35f) {
                        const float tau = __fdividef(aqq - app, 2.f*apq);
                        float t = __fdividef(1.f, fabsf(tau) + sqrtf(1.f + tau*tau));
                        if (tau < 0.f) t = -t;
                        c = rsqrtf(1.f + t*t);
                        sv = t*c;
                    }
                    pr_[tid] = p; qr_[tid] = q; rc_[tid] = c; rs_[tid] = sv;

                    dsmem_st_v2f(mapa_u32(cbuf_u + (uint32_t)(s*132 + 2*tid)*4u, 1u), c, sv);
                    if (tid == 0)
                        dsmem_st_b32(mapa_u32(cbuf_u + (uint32_t)(s*132 + 128)*4u, 1u), 0u);
                    mbar_arrive_remote(mapa_u32(full_u + s*8, 1u));
                }
                __syncthreads();

                for (int it = tid; it < 4096; it += 1024) {
                    const int m = it >> 6, l = it & 63;
                    const int pm = pr_[m], qm = qr_[m], pl = pr_[l], ql = qr_[l];
                    const float cm = rc_[m], smv = rs_[m], cl = rc_[l], sl = rs_[l];
                    const float a00 = A[pm*PITCH + pl], a01 = A[pm*PITCH + ql];
                    const float a10 = A[qm*PITCH + pl], a11 = A[qm*PITCH + ql];
                    const float r00 = cm*a00 - smv*a10, r01 = cm*a01 - smv*a11;
                    const float r10 = smv*a00 + cm*a10, r11 = smv*a01 + cm*a11;
                    A[pm*PITCH + pl] = cl*r00 - sl*r01;
                    A[pm*PITCH + ql] = sl*r00 + cl*r01;
                    A[qm*PITCH + pl] = cl*r10 - sl*r11;
                    A[qm*PITCH + ql] = sl*r10 + cl*r11;
                }
                __syncthreads();

                iter++;
                if (++tmod == 127) tmod = 0;
            }

            float off2 = 0.f, dia2 = 0.f;
            for (int e = tid; e < DD*DD; e += 1024) {
                const int i = e >> 7, j = e & 127;
                const float a = A[i*PITCH + j];
                if (i == j) dia2 += a*a; else off2 += a*a;
            }
#pragma unroll
            for (int o = 16; o > 0; o >>= 1) {
                off2 += __shfl_down_sync(0xffffffff, off2, o);
                dia2 += __shfl_down_sync(0xffffffff, dia2, o);
            }
            if (lane == 0) { red_o[wid] = off2; red_d[wid] = dia2; }
            __syncthreads();
            if (tid == 0) {
                float o = 0.f, d = 0.f;
#pragma unroll
                for (int w = 0; w < 32; w++) { o += red_o[w]; d += red_d[w]; }
                s_done = (o <= 1e-9f*d) ? 1 : 0;
            }
            __syncthreads();
            done = s_done;
            __syncthreads();
        }

        // ---- final packet: rank map + flag=1 ----
        {
            const int s = iter & 3;
            if (tid == 0)
                mbar_wait(empty_u + s*8, (uint32_t)((((iter >> 2)) ^ 1) & 1));
            __syncthreads();

            if (tid < DD) ev[tid] = A[tid*PITCH + tid];
            __syncthreads();
            if (tid < DD) {
                const float e = ev[tid];
                int r_ = 0;
                for (int j = 0; j < DD; j++) {
                    const float ej = ev[j];
                    if (ej > e || (ej == e && j < tid)) r_++;
                }
                rank_[tid] = r_;
            }
            __syncthreads();
            if (tid < 64) {
                dsmem_st_v2f(mapa_u32(cbuf_u + (uint32_t)(s*132 + 2*tid)*4u, 1u),
                             __int_as_float(rank_[2*tid]), __int_as_float(rank_[2*tid+1]));
                if (tid == 0)
                    dsmem_st_b32(mapa_u32(cbuf_u + (uint32_t)(s*132 + 128)*4u, 1u), 1u);
                mbar_arrive_remote(mapa_u32(full_u + s*8, 1u));
            }
        }
    } else {
        // =============== rank 1: V-side ===============
        float* Vm = sm;
        for (int e = tid; e < DD*DD; e += 1024) {
            const int i = e >> 7, j = e & 127;
            Vm[i*PITCH + j] = (i == j) ? 1.f : 0.f;
        }
        __syncthreads();

        const int lpair = tid >> 4;     // 0..63: this thread's rotation pair
        const int kk0   = tid & 15;     // k = kk0 + 16*j

        // bounded by max packets rank0 can send (MAXSWEEP*127 rotations + final)
        int tm = 0;
        for (int it = 0; it <= MAXSWEEP*127; it++) {
            const int s = it & 3;
            mbar_wait(full_u + s*8, (uint32_t)((it >> 2) & 1));

            const int flag = __float_as_int(cbuf[s][128]);
            if (flag) {
                float* Bb = g_B + (size_t)bh*DD*RR;
                for (int x = tid; x < DD*DD; x += 1024) {
                    const int k = x >> 7, d = x & 127;
                    const int r = __float_as_int(cbuf[s][d]);
                    if (r < RR) Bb[k*RR + r] = Vm[k*PITCH + d];
                }
                break;
            }

            // V <- V J: 16 threads per pair, pairing computed once
            int pl;
            if (lpair == 0) pl = 0;
            else { int r = lpair - 1 - tm; if (r < 0) r += 127; pl = 1 + r; }
            int r2 = 126 - lpair - tm; if (r2 < 0) r2 += 127;
            const int ql = 1 + r2;
            const float cl = cbuf[s][2*lpair], sl = cbuf[s][2*lpair+1];
#pragma unroll
            for (int j = 0; j < 8; j++) {
                const int k = kk0 + j*16;
                const float vp = Vm[k*PITCH + pl], vq = Vm[k*PITCH + ql];
                Vm[k*PITCH + pl] = cl*vp - sl*vq;
                Vm[k*PITCH + ql] = sl*vp + cl*vq;
            }
            __syncthreads();
            if (tid == 0) mbar_arrive_remote(mapa_u32(empty_u + s*8, 0u));
            if (++tm == 127) tm = 0;
        }
    }

    CLUSTER_SYNC();
}

// =========================================================================
// Kernel 3: projection  Y = X * B * scale  ([bh][rows][128] -> [..][32])
// v2: X staged in 32-wide d-chunks -> smem 34816 B -> 4 CTAs/SM (occupancy).
// grid (64, nrows/128), 256 threads, 2x8 register tile per thread.
// =========================================================================
#define XPC 36     // chunk pitch
__global__ void proj_kernel(const float* __restrict__ X, int is_q)
{
    extern __shared__ float psm[];
    float* Xs = psm;                 // [128][36]  (32-wide d-chunk)
    float* Bs = psm + 128*XPC;       // [128][32]

    const int bh = blockIdx.x;
    const int t0 = blockIdx.y*128;
    const int nrows = is_q ? QL : KL;
    const float scale = is_q ? 0.17677669529663687f : 1.0f;  // 1/sqrt(32)
    float* Y = is_q ? g_Qp : g_Kp;

    const int tid = threadIdx.x;
    const float4* Bsrc = (const float4*)(g_B + (size_t)bh*DD*RR);
    for (int i = tid; i < DD*RR/4; i += 256) ((float4*)Bs)[i] = Bsrc[i];

    const float4* Xb = (const float4*)(X + ((size_t)bh*nrows + t0)*DD);

    const int row0 = (tid >> 2)*2, c0 = (tid & 3)*8;
    float a0[8], a1[8];
#pragma unroll
    for (int j = 0; j < 8; j++) { a0[j] = 0.f; a1[j] = 0.f; }

    for (int d0 = 0; d0 < DD; d0 += 32) {
        __syncthreads();
        // stage X[:, d0:d0+32]: 128 rows x 8 float4
        for (int i = tid; i < 128*8; i += 256) {
            const int r = i >> 3, c = i & 7;
            *(float4*)&Xs[r*XPC + c*4] = Xb[r*(DD/4) + (d0 >> 2) + c];
        }
        __syncthreads();

#pragma unroll
        for (int dd = 0; dd < 32; dd++) {
            const int d = d0 + dd;
            const float x0 = Xs[row0*XPC + dd];
            const float x1 = Xs[(row0+1)*XPC + dd];
            float b[8];
            *(float4*)&b[0] = *(float4*)&Bs[d*RR + c0];
            *(float4*)&b[4] = *(float4*)&Bs[d*RR + c0 + 4];
#pragma unroll
            for (int j = 0; j < 8; j++) { a0[j] += x0*b[j]; a1[j] += x1*b[j]; }
        }
    }
    float* Yb = Y + ((size_t)bh*nrows + t0 + row0)*RR + c0;
    float4 o0, o1;
    o0.x=a0[0]*scale; o0.y=a0[1]*scale; o0.z=a0[2]*scale; o0.w=a0[3]*scale;
    o1.x=a0[4]*scale; o1.y=a0[5]*scale; o1.z=a0[6]*scale; o1.w=a0[7]*scale;
    *(float4*)&Yb[0] = o0; *(float4*)&Yb[4] = o1;
    o0.x=a1[0]*scale; o0.y=a1[1]*scale; o0.z=a1[2]*scale; o0.w=a1[3]*scale;
    o1.x=a1[4]*scale; o1.y=a1[5]*scale; o1.z=a1[6]*scale; o1.w=a1[7]*scale;
    *(float4*)&Yb[RR] = o0; *(float4*)&Yb[RR+4] = o1;
}

// =========================================================================
// Kernel 4: attention  out = softmax(Qp Kp^T) V   (fp32)
// No max subtraction needed: |score| <= 22.6 -> exp/sums safe in fp32.
// TQ=128, 256 threads, TK=32. S-compute AND PV packed f32x2.
// S accumulators hold column pairs (s[j], s[j+1]). grid (64, 4).
// =========================================================================
__global__ void attn_kernel(const float* __restrict__ V, float* __restrict__ Out)
{
    extern __shared__ float asm_[];
    float* Qs  = asm_;                    // [128][33]
    float* Kst = asm_ + 128*33;           // [32][36]  transposed K chunk
    float* Vs  = asm_ + 128*33 + 32*36;   // [32][132]
    float* St  = Vs + 32*132;             // [32][132] transposed exp(scores)

    __shared__ float Lp[128][4];
    __shared__ float lrow[128];

    const int bh = blockIdx.x;
    const int q0 = blockIdx.y*128;

    const int tid = threadIdx.x;               // 256 threads
    const int rg = tid >> 4, cg = tid & 15;
    const int r0 = rg*8, c0v = cg*8;           // O tile: rows r0.., cols c0v..
    const int sa = (tid >> 2)*2, sb = (tid & 3)*8;   // S tile: 2x8
    const int hcol = tid & 3;

    const float* Qp = g_Qp + ((size_t)bh*QL + q0)*RR;
    for (int i = tid; i < 128*RR; i += 256) {
        const int r = i >> 5, c = i & 31;
        Qs[r*33 + c] = Qp[i];
    }

    u64 acc2[8][4];
#pragma unroll
    for (int i = 0; i < 8; i++)
#pragma unroll
        for (int j = 0; j < 4; j++) acc2[i][j] = 0ull;
    float lp0 = 0.f, lp1 = 0.f;
    __syncthreads();

    for (int kc = 0; kc < KL/32; kc++) {
        const int k0 = kc*32;
        const float* Kp = g_Kp + ((size_t)bh*KL + k0)*RR;
        for (int i = tid; i < 32*RR; i += 256) {
            const int r = i >> 5, c = i & 31;
            Kst[c*36 + r] = Kp[i];                  // transpose on store
        }
        const float4* Vb = (const float4*)(V + ((size_t)bh*KL + k0)*DD);
        for (int i = tid; i < 32*DD/4; i += 256) {
            const int r = i >> 5, c = i & 31;
            *(float4*)&Vs[r*132 + c*4] = Vb[i];
        }
        __syncthreads();

        // ---- S = exp(Qp Kp^T): f32x2 over column pairs ----
        u64 sA[4], sB[4];   // row sa / row sa+1, col pairs (sb+2j, sb+2j+1)
#pragma unroll
        for (int j = 0; j < 4; j++) { sA[j] = 0ull; sB[j] = 0ull; }
        for (int k = 0; k < RR; k++) {
            const float qa = Qs[sa*33 + k], qb = Qs[(sa+1)*33 + k];
            const u64 qa2 = pk2(qa, qa), qb2 = pk2(qb, qb);
            const ulonglong2* kp = (const ulonglong2*)&Kst[k*36 + sb];
            const ulonglong2 t0v = kp[0], t1v = kp[1];
            u64 k2[4]; k2[0] = t0v.x; k2[1] = t0v.y; k2[2] = t1v.x; k2[3] = t1v.y;
#pragma unroll
            for (int j = 0; j < 4; j++) {
                sA[j] = fma2(qa2, k2[j], sA[j]);
                sB[j] = fma2(qb2, k2[j], sB[j]);
            }
        }
#pragma unroll
        for (int j = 0; j < 4; j++) {
            float a0, a1, b0, b1;
            up2(sA[j], a0, a1);
            up2(sB[j], b0, b1);
            const float pa0 = __expf(a0), pa1 = __expf(a1);
            const float pb0 = __expf(b0), pb1 = __expf(b1);
            lp0 += pa0 + pa1; lp1 += pb0 + pb1;
            *(float2*)&St[(sb+2*j)*132   + sa] = make_float2(pa0, pb0);
            *(float2*)&St[(sb+2*j+1)*132 + sa] = make_float2(pa1, pb1);
        }
        __syncthreads();

        // ---- O += P V  (packed f32x2 over output columns) ----
        for (int j = 0; j < 32; j++) {
            float p8[8];
            *(float4*)&p8[0] = *(float4*)&St[j*132 + r0];
            *(float4*)&p8[4] = *(float4*)&St[j*132 + r0 + 4];
            const ulonglong2* vp = (const ulonglong2*)&Vs[j*132 + c0v];
            const ulonglong2 t0v = vp[0], t1v = vp[1];
            u64 v2[4]; v2[0] = t0v.x; v2[1] = t0v.y; v2[2] = t1v.x; v2[3] = t1v.y;
#pragma unroll
            for (int i = 0; i < 8; i++) {
                const u64 p2 = pk2(p8[i], p8[i]);
#pragma unroll
                for (int jj = 0; jj < 4; jj++) acc2[i][jj] = fma2(p2, v2[jj], acc2[i][jj]);
            }
        }
        __syncthreads();
    }

    // ---- reduce l partials (deterministic) ----
    Lp[sa][hcol]   = lp0;
    Lp[sa+1][hcol] = lp1;
    __syncthreads();
    if (tid < 128)
        lrow[tid] = ((Lp[tid][0] + Lp[tid][1]) + (Lp[tid][2] + Lp[tid][3]));
    __syncthreads();

    // ---- epilogue (packed stores) ----
    float* Ob = Out + ((size_t)bh*QL + q0)*DD;
#pragma unroll
    for (int i = 0; i < 8; i++) {
        const float inv = 1.f/lrow[r0+i];
        const u64 inv2 = pk2(inv, inv);
        ulonglong2 o0, o1;
        o0.x = mul2(inv2, acc2[i][0]); o0.y = mul2(inv2, acc2[i][1]);
        o1.x = mul2(inv2, acc2[i][2]); o1.y = mul2(inv2, acc2[i][3]);
        ((ulonglong2*)&Ob[(r0+i)*DD + c0v])[0] = o0;
        ((ulonglong2*)&Ob[(r0+i)*DD + c0v])[1] = o1;
    }
}

// =========================================================================
extern "C" void kernel_launch(void* const* d_in, const int* in_sizes, int n_in,
                              void* d_out, int out_size)
{
    const float* Q = (const float*)d_in[0];
    const float* K = (const float*)d_in[1];
    const float* V = (const float*)d_in[2];
    float* Out = (float*)d_out;

    const int jac_smem  = DD*PITCH*(int)sizeof(float);          // 66048 B per CTA
    const int proj_smem = (128*XPC + 128*RR)*(int)sizeof(float); // 34816 B
    const int attn_smem = (128*33 + 32*36 + 32*132 + 32*132)*(int)sizeof(float); // 55296 B
    cudaFuncSetAttribute(jacobi_cluster_kernel,
                         cudaFuncAttributeMaxDynamicSharedMemorySize, jac_smem);
    cudaFuncSetAttribute(proj_kernel,
                         cudaFuncAttributeMaxDynamicSharedMemorySize, proj_smem);
    cudaFuncSetAttribute(attn_kernel,
                         cudaFuncAttributeMaxDynamicSharedMemorySize, attn_smem);

    gram_partial_kernel<<<dim3(BH, NCH), 256>>>(K);
    jacobi_cluster_kernel<<<2*BH, 1024, jac_smem>>>();
    proj_kernel<<<dim3(BH, KL/128), 256, proj_smem>>>(K, 0);
    proj_kernel<<<dim3(BH, QL/128), 256, proj_smem>>>(Q, 1);
    attn_kernel<<<dim3(BH, QL/128), 256, attn_smem>>>(V, Out);
}

// round 12
// speedup vs baseline: 1.0296x; 1.0296x over previous
#include <cuda_runtime.h>
#include <math.h>
#include <stdint.h>

#define BH 64
#define QL 512
#define KL 4096
#define DD 128
#define RR 32
#define NCH 8
#define CHUNK 512          // KL / NCH
#define MAXSWEEP 8
#define PITCH 129          // smem pitch for 128x128 matrices

typedef unsigned long long u64;

// ---------------- packed f32x2 helpers (sm_103a) ----------------
__device__ __forceinline__ u64 pk2(float x, float y) {
    u64 r; asm("mov.b64 %0,{%1,%2};" : "=l"(r) : "f"(x), "f"(y)); return r;
}
__device__ __forceinline__ void up2(u64 v, float& lo, float& hi) {
    asm("mov.b64 {%0,%1},%2;" : "=f"(lo), "=f"(hi) : "l"(v));
}
__device__ __forceinline__ u64 fma2(u64 a, u64 b, u64 c) {
    u64 d; asm("fma.rn.f32x2 %0,%1,%2,%3;" : "=l"(d) : "l"(a), "l"(b), "l"(c)); return d;
}
__device__ __forceinline__ u64 mul2(u64 a, u64 b) {
    u64 d; asm("mul.rn.f32x2 %0,%1,%2;" : "=l"(d) : "l"(a), "l"(b)); return d;
}

// ---------------- device scratch (static allocation only) ----------------
__device__ float g_Gpart[BH*NCH*DD*DD];   // partial Gram matrices
__device__ float g_mspart[BH*NCH*DD];     // partial column sums
__device__ float g_B[BH*DD*RR];           // top-32 eigenbasis  [bh][d][r]
__device__ float g_Kp[(size_t)BH*KL*RR];  // K projected
__device__ float g_Qp[(size_t)BH*QL*RR];  // Q projected (pre-scaled)

// ---------------- cluster / mbarrier helpers ----------------
__device__ __forceinline__ uint32_t s2u(const void* p) {
    uint32_t a;
    asm("{ .reg .u64 t; cvta.to.shared.u64 t, %1; cvt.u32.u64 %0, t; }"
        : "=r"(a) : "l"(p));
    return a;
}
__device__ __forceinline__ uint32_t ctarank() {
    uint32_t r; asm("mov.u32 %0, %%cluster_ctarank;" : "=r"(r)); return r;
}
__device__ __forceinline__ uint32_t mapa_u32(uint32_t a, uint32_t r) {
    uint32_t o; asm("mapa.shared::cluster.u32 %0, %1, %2;" : "=r"(o) : "r"(a), "r"(r));
    return o;
}
__device__ __forceinline__ void mbar_init(uint32_t a, uint32_t cnt) {
    asm volatile("mbarrier.init.shared.b64 [%0], %1;" :: "r"(a), "r"(cnt) : "memory");
}
__device__ __forceinline__ void mbar_arrive_remote(uint32_t ra) {
    asm volatile("mbarrier.arrive.release.cluster.shared::cluster.b64 _, [%0];"
                 :: "r"(ra) : "memory");
}
__device__ __forceinline__ void dsmem_st_v2f(uint32_t ra, float x, float y) {
    asm volatile("st.shared::cluster.v2.f32 [%0], {%1,%2};"
                 :: "r"(ra), "f"(x), "f"(y) : "memory");
}
__device__ __forceinline__ void dsmem_st_b32(uint32_t ra, uint32_t v) {
    asm volatile("st.shared::cluster.b32 [%0], %1;" :: "r"(ra), "r"(v) : "memory");
}
// blocking parity wait, cluster-scope acquire
__device__ __forceinline__ void mbar_wait(uint32_t a, uint32_t parity) {
    uint32_t done;
    asm volatile(
        "{\n\t.reg .pred p;\n\t"
        "mbarrier.try_wait.parity.acquire.cluster.shared::cta.b64 p, [%1], %2;\n\t"
        "selp.b32 %0, 1, 0, p;\n\t}"
        : "=r"(done) : "r"(a), "r"(parity) : "memory");
    if (!done) {
        asm volatile(
            "{\n\t.reg .pred P1;\n\t"
            "WL_%=:\n\t"
            "mbarrier.try_wait.parity.acquire.cluster.shared::cta.b64 P1, [%0], %1, 0x989680;\n\t"
            "@P1 bra.uni WD_%=;\n\t"
            "bra.uni WL_%=;\n\t"
            "WD_%=:\n\t}"
            :: "r"(a), "r"(parity) : "memory");
    }
}
#define CLUSTER_SYNC() do { \
    asm volatile("barrier.cluster.arrive.aligned;" ::: "memory"); \
    asm volatile("barrier.cluster.wait.aligned;"   ::: "memory"); \
} while (0)

// =========================================================================
// Kernel 1: partial Gram  G_chunk = K_chunk^T K_chunk   + column sums
// grid (64, 8), 256 threads.  8x8 register tile, f32x2 accumulation.
// =========================================================================
__global__ void gram_partial_kernel(const float* __restrict__ K)
{
    const int bh = blockIdx.x, ch = blockIdx.y;
    const float* Kb = K + ((size_t)bh*KL + (size_t)ch*CHUNK)*DD;

    __shared__ __align__(16) float Ks[16][DD];

    const int tid = threadIdx.x;
    const int ti = tid >> 4, tj = tid & 15;
    u64 acc2[8][4];
#pragma unroll
    for (int i = 0; i < 8; i++)
#pragma unroll
        for (int j = 0; j < 4; j++) acc2[i][j] = 0ull;
    float cs = 0.f;

    for (int n0 = 0; n0 < CHUNK; n0 += 16) {
        const float4* src = (const float4*)(Kb + (size_t)n0*DD);
        float4* dst = (float4*)(&Ks[0][0]);
#pragma unroll
        for (int i = tid; i < 16*DD/4; i += 256) dst[i] = src[i];
        __syncthreads();

        for (int n = 0; n < 16; n++) {
            float a[8];
            *(float4*)&a[0] = *(float4*)&Ks[n][ti*8];
            *(float4*)&a[4] = *(float4*)&Ks[n][ti*8+4];
            u64 b2[4];
            const ulonglong2* bp = (const ulonglong2*)&Ks[n][tj*8];
            ulonglong2 t0 = bp[0], t1 = bp[1];
            b2[0] = t0.x; b2[1] = t0.y; b2[2] = t1.x; b2[3] = t1.y;
#pragma unroll
            for (int i = 0; i < 8; i++) {
                const u64 a2 = pk2(a[i], a[i]);
#pragma unroll
                for (int j = 0; j < 4; j++) acc2[i][j] = fma2(a2, b2[j], acc2[i][j]);
            }
        }
        if (tid < DD) {
#pragma unroll
            for (int n = 0; n < 16; n++) cs += Ks[n][tid];
        }
        __syncthreads();
    }

    float* Gp = g_Gpart + ((size_t)(bh*NCH + ch))*DD*DD;
#pragma unroll
    for (int i = 0; i < 8; i++) {
        ulonglong2* op = (ulonglong2*)&Gp[(ti*8+i)*DD + tj*8];
        ulonglong2 o0, o1;
        o0.x = acc2[i][0]; o0.y = acc2[i][1];
        o1.x = acc2[i][2]; o1.y = acc2[i][3];
        op[0] = o0; op[1] = o1;
    }
    if (tid < DD) g_mspart[(bh*NCH + ch)*DD + tid] = cs;
}

// =========================================================================
// Kernel 2: cluster-split Jacobi. 2 CTAs per bh (rank0: A; rank1: V).
// Coefficients rank0 -> rank1 via 4-slot dsmem ring + mbarriers.
// rank1 V-update: R10 layout (whole warp on one pair -> conflict-free).
// grid 128 (cluster 2), 1024 threads, 66048 B dynamic smem per CTA.
// =========================================================================
__global__ void __launch_bounds__(1024, 1) __cluster_dims__(2, 1, 1)
jacobi_cluster_kernel()
{
    extern __shared__ float sm[];     // rank0: A[128][129]; rank1: Vm[128][129]

    __shared__ float cbuf[4][132];    // slot: 64x(c,s) interleaved, [128]=flag
    __shared__ __align__(8) unsigned long long mbar[8];  // [0..3]=empty, [4..7]=full
    __shared__ float ssum[DD];
    __shared__ int   pr_[64], qr_[64];
    __shared__ float rc_[64], rs_[64];
    __shared__ float red_o[32], red_d[32];
    __shared__ float ev[DD];
    __shared__ int   rank_[DD];
    __shared__ int   s_done;

    const int bh  = blockIdx.x >> 1;
    const int tid = threadIdx.x;
    const int lane = tid & 31, wid = tid >> 5;
    const uint32_t rk = ctarank();

    const uint32_t cbuf_u  = s2u(&cbuf[0][0]);
    const uint32_t empty_u = s2u(&mbar[0]);
    const uint32_t full_u  = s2u(&mbar[4]);

    if (tid == 0) {
        if (rk == 0) { for (int i = 0; i < 4; i++) mbar_init(empty_u + i*8, 1); }
        else         { for (int i = 0; i < 4; i++) mbar_init(full_u  + i*8, 64); }
    }
    __syncthreads();
    CLUSTER_SYNC();

    if (rk == 0) {
        // =============== rank 0: A-side ===============
        float* A = sm;

        if (tid < DD) {
            float t = 0.f;
#pragma unroll
            for (int c = 0; c < NCH; c++) t += g_mspart[(bh*NCH + c)*DD + tid];
            ssum[tid] = t;
        }
        __syncthreads();
        const float invn = 1.f/(float)KL;
        for (int e = tid; e < DD*DD; e += 1024) {
            const int i = e >> 7, j = e & 127;
            float t = 0.f;
#pragma unroll
            for (int c = 0; c < NCH; c++) t += g_Gpart[((size_t)(bh*NCH + c) << 14) + e];
            A[i*PITCH + j] = t - ssum[i]*ssum[j]*invn;
        }
        __syncthreads();

        int iter = 0, tmod = 0, done = 0;
        for (int sweep = 0; sweep < MAXSWEEP && !done; sweep++) {
            for (int step = 0; step < 127; step++) {
                const int s = iter & 3;

                if (tid < 64) {
                    if (iter >= 4)
                        mbar_wait(empty_u + s*8, (uint32_t)((((iter >> 2)) ^ 1) & 1));

                    int p;
                    if (tid == 0) p = 0;
                    else { int r = tid - 1 - tmod; if (r < 0) r += 127; p = 1 + r; }
                    int r2 = 126 - tid - tmod; if (r2 < 0) r2 += 127;
                    const int q = 1 + r2;

                    const float app = A[p*PITCH + p];
                    const float aqq = A[q*PITCH + q];
                    const float apq = A[p*PITCH + q];
                    float c = 1.f, sv = 0.f;
                    if (fabsf(apq) > 1e-10f*(fabsf(app) + fabsf(aqq)) + 1e-35f) {
                        const float tau = __fdividef(aqq - app, 2.f*apq);
                        float t = __fdividef(1.f, fabsf(tau) + sqrtf(1.f + tau*tau));
                        if (tau < 0.f) t = -t;
                        c = rsqrtf(1.f + t*t);
                        sv = t*c;
                    }
                    pr_[tid] = p; qr_[tid] = q; rc_[tid] = c; rs_[tid] = sv;

                    dsmem_st_v2f(mapa_u32(cbuf_u + (uint32_t)(s*132 + 2*tid)*4u, 1u), c, sv);
                    if (tid == 0)
                        dsmem_st_b32(mapa_u32(cbuf_u + (uint32_t)(s*132 + 128)*4u, 1u), 0u);
                    mbar_arrive_remote(mapa_u32(full_u + s*8, 1u));
                }
                __syncthreads();

                for (int it = tid; it < 4096; it += 1024) {
                    const int m = it >> 6, l = it & 63;
                    const int pm = pr_[m], qm = qr_[m], pl = pr_[l], ql = qr_[l];
                    const float cm = rc_[m], smv = rs_[m], cl = rc_[l], sl = rs_[l];
                    const float a00 = A[pm*PITCH + pl], a01 = A[pm*PITCH + ql];
                    const float a10 = A[qm*PITCH + pl], a11 = A[qm*PITCH + ql];
                    const float r00 = cm*a00 - smv*a10, r01 = cm*a01 - smv*a11;
                    const float r10 = smv*a00 + cm*a10, r11 = smv*a01 + cm*a11;
                    A[pm*PITCH + pl] = cl*r00 - sl*r01;
                    A[pm*PITCH + ql] = sl*r00 + cl*r01;
                    A[qm*PITCH + pl] = cl*r10 - sl*r11;
                    A[qm*PITCH + ql] = sl*r10 + cl*r11;
                }
                __syncthreads();

                iter++;
                if (++tmod == 127) tmod = 0;
            }

            float off2 = 0.f, dia2 = 0.f;
            for (int e = tid; e < DD*DD; e += 1024) {
                const int i = e >> 7, j = e & 127;
                const float a = A[i*PITCH + j];
                if (i == j) dia2 += a*a; else off2 += a*a;
            }
#pragma unroll
            for (int o = 16; o > 0; o >>= 1) {
                off2 += __shfl_down_sync(0xffffffff, off2, o);
                dia2 += __shfl_down_sync(0xffffffff, dia2, o);
            }
            if (lane == 0) { red_o[wid] = off2; red_d[wid] = dia2; }
            __syncthreads();
            if (tid == 0) {
                float o = 0.f, d = 0.f;
#pragma unroll
                for (int w = 0; w < 32; w++) { o += red_o[w]; d += red_d[w]; }
                s_done = (o <= 1e-9f*d) ? 1 : 0;
            }
            __syncthreads();
            done = s_done;
            __syncthreads();
        }

        // ---- final packet: rank map + flag=1 ----
        {
            const int s = iter & 3;
            if (tid == 0)
                mbar_wait(empty_u + s*8, (uint32_t)((((iter >> 2)) ^ 1) & 1));
            __syncthreads();

            if (tid < DD) ev[tid] = A[tid*PITCH + tid];
            __syncthreads();
            if (tid < DD) {
                const float e = ev[tid];
                int r_ = 0;
                for (int j = 0; j < DD; j++) {
                    const float ej = ev[j];
                    if (ej > e || (ej == e && j < tid)) r_++;
                }
                rank_[tid] = r_;
            }
            __syncthreads();
            if (tid < 64) {
                dsmem_st_v2f(mapa_u32(cbuf_u + (uint32_t)(s*132 + 2*tid)*4u, 1u),
                             __int_as_float(rank_[2*tid]), __int_as_float(rank_[2*tid+1]));
                if (tid == 0)
                    dsmem_st_b32(mapa_u32(cbuf_u + (uint32_t)(s*132 + 128)*4u, 1u), 1u);
                mbar_arrive_remote(mapa_u32(full_u + s*8, 1u));
            }
        }
    } else {
        // =============== rank 1: V-side ===============
        float* Vm = sm;
        for (int e = tid; e < DD*DD; e += 1024) {
            const int i = e >> 7, j = e & 127;
            Vm[i*PITCH + j] = (i == j) ? 1.f : 0.f;
        }
        __syncthreads();

        // bounded by max packets rank0 can send (MAXSWEEP*127 rotations + final)
        int tm = 0;
        for (int it = 0; it <= MAXSWEEP*127; it++) {
            const int s = it & 3;
            mbar_wait(full_u + s*8, (uint32_t)((it >> 2) & 1));

            const int flag = __float_as_int(cbuf[s][128]);
            if (flag) {
                float* Bb = g_B + (size_t)bh*DD*RR;
                for (int x = tid; x < DD*DD; x += 1024) {
                    const int k = x >> 7, d = x & 127;
                    const int r = __float_as_int(cbuf[s][d]);
                    if (r < RR) Bb[k*RR + r] = Vm[k*PITCH + d];
                }
                break;
            }

            // V <- V J (R10 layout: whole warp on one pair -> conflict-free)
            for (int x = tid; x < 8192; x += 1024) {
                const int l = x >> 7, k = x & 127;
                int pl;
                if (l == 0) pl = 0;
                else { int r = l - 1 - tm; if (r < 0) r += 127; pl = 1 + r; }
                int r2 = 126 - l - tm; if (r2 < 0) r2 += 127;
                const int ql = 1 + r2;
                const float cl = cbuf[s][2*l], sl = cbuf[s][2*l+1];
                const float vp = Vm[k*PITCH + pl], vq = Vm[k*PITCH + ql];
                Vm[k*PITCH + pl] = cl*vp - sl*vq;
                Vm[k*PITCH + ql] = sl*vp + cl*vq;
            }
            __syncthreads();
            if (tid == 0) mbar_arrive_remote(mapa_u32(empty_u + s*8, 0u));
            if (++tm == 127) tm = 0;
        }
    }

    CLUSTER_SYNC();
}

// =========================================================================
// Kernel 3: projection  Y = X * B * scale  ([bh][rows][128] -> [..][32])
// grid (64, nrows/128), 256 threads, 2x8 register tile per thread. (R10)
// =========================================================================
#define XP 132
__global__ void proj_kernel(const float* __restrict__ X, int is_q)
{
    extern __shared__ float psm[];
    float* Xs = psm;                 // [128][XP]
    float* Bs = psm + 128*XP;        // [128][32]

    const int bh = blockIdx.x;
    const int t0 = blockIdx.y*128;
    const int nrows = is_q ? QL : KL;
    const float scale = is_q ? 0.17677669529663687f : 1.0f;  // 1/sqrt(32)
    float* Y = is_q ? g_Qp : g_Kp;

    const int tid = threadIdx.x;
    const float4* Bsrc = (const float4*)(g_B + (size_t)bh*DD*RR);
    for (int i = tid; i < DD*RR/4; i += 256) ((float4*)Bs)[i] = Bsrc[i];

    const float4* Xb = (const float4*)(X + ((size_t)bh*nrows + t0)*DD);
    for (int i = tid; i < 128*DD/4; i += 256) {
        const int r = i >> 5, c = i & 31;
        *(float4*)&Xs[r*XP + c*4] = Xb[i];
    }
    __syncthreads();

    const int row0 = (tid >> 2)*2, c0 = (tid & 3)*8;
    float a0[8], a1[8];
#pragma unroll
    for (int j = 0; j < 8; j++) { a0[j] = 0.f; a1[j] = 0.f; }

    for (int d = 0; d < DD; d++) {
        const float x0 = Xs[row0*XP + d];
        const float x1 = Xs[(row0+1)*XP + d];
        float b[8];
        *(float4*)&b[0] = *(float4*)&Bs[d*RR + c0];
        *(float4*)&b[4] = *(float4*)&Bs[d*RR + c0 + 4];
#pragma unroll
        for (int j = 0; j < 8; j++) { a0[j] += x0*b[j]; a1[j] += x1*b[j]; }
    }
    float* Yb = Y + ((size_t)bh*nrows + t0 + row0)*RR + c0;
    float4 o0, o1;
    o0.x=a0[0]*scale; o0.y=a0[1]*scale; o0.z=a0[2]*scale; o0.w=a0[3]*scale;
    o1.x=a0[4]*scale; o1.y=a0[5]*scale; o1.z=a0[6]*scale; o1.w=a0[7]*scale;
    *(float4*)&Yb[0] = o0; *(float4*)&Yb[4] = o1;
    o0.x=a1[0]*scale; o0.y=a1[1]*scale; o0.z=a1[2]*scale; o0.w=a1[3]*scale;
    o1.x=a1[4]*scale; o1.y=a1[5]*scale; o1.z=a1[6]*scale; o1.w=a1[7]*scale;
    *(float4*)&Yb[RR] = o0; *(float4*)&Yb[RR+4] = o1;
}

// =========================================================================
// Kernel 4: attention  out = softmax(Qp Kp^T) V   (fp32)
// No max subtraction needed: |score| <= 22.6 -> exp/sums safe in fp32.
// TQ=128, 256 threads, TK=32. S-compute AND PV packed f32x2.
// grid (64, 4). (single change vs R10: S-compute packed)
// =========================================================================
__global__ void attn_kernel(const float* __restrict__ V, float* __restrict__ Out)
{
    extern __shared__ float asm_[];
    float* Qs  = asm_;                    // [128][33]
    float* Kst = asm_ + 128*33;           // [32][36]  transposed K chunk
    float* Vs  = asm_ + 128*33 + 32*36;   // [32][132]
    float* St  = Vs + 32*132;             // [32][132] transposed exp(scores)

    __shared__ float Lp[128][4];
    __shared__ float lrow[128];

    const int bh = blockIdx.x;
    const int q0 = blockIdx.y*128;

    const int tid = threadIdx.x;               // 256 threads
    const int rg = tid >> 4, cg = tid & 15;
    const int r0 = rg*8, c0v = cg*8;           // O tile: rows r0.., cols c0v..
    const int sa = (tid >> 2)*2, sb = (tid & 3)*8;   // S tile: 2x8
    const int hcol = tid & 3;

    const float* Qp = g_Qp + ((size_t)bh*QL + q0)*RR;
    for (int i = tid; i < 128*RR; i += 256) {
        const int r = i >> 5, c = i & 31;
        Qs[r*33 + c] = Qp[i];
    }

    u64 acc2[8][4];
#pragma unroll
    for (int i = 0; i < 8; i++)
#pragma unroll
        for (int j = 0; j < 4; j++) acc2[i][j] = 0ull;
    float lp0 = 0.f, lp1 = 0.f;
    __syncthreads();

    for (int kc = 0; kc < KL/32; kc++) {
        const int k0 = kc*32;
        const float* Kp = g_Kp + ((size_t)bh*KL + k0)*RR;
        for (int i = tid; i < 32*RR; i += 256) {
            const int r = i >> 5, c = i & 31;
            Kst[c*36 + r] = Kp[i];                  // transpose on store
        }
        const float4* Vb = (const float4*)(V + ((size_t)bh*KL + k0)*DD);
        for (int i = tid; i < 32*DD/4; i += 256) {
            const int r = i >> 5, c = i & 31;
            *(float4*)&Vs[r*132 + c*4] = Vb[i];
        }
        __syncthreads();

        // ---- S = exp(Qp Kp^T): f32x2 over column pairs ----
        u64 sA[4], sB[4];   // row sa / row sa+1, col pairs (sb+2j, sb+2j+1)
#pragma unroll
        for (int j = 0; j < 4; j++) { sA[j] = 0ull; sB[j] = 0ull; }
        for (int k = 0; k < RR; k++) {
            const float qa = Qs[sa*33 + k], qb = Qs[(sa+1)*33 + k];
            const u64 qa2 = pk2(qa, qa), qb2 = pk2(qb, qb);
            const ulonglong2* kp = (const ulonglong2*)&Kst[k*36 + sb];
            const ulonglong2 t0v = kp[0], t1v = kp[1];
            u64 k2[4]; k2[0] = t0v.x; k2[1] = t0v.y; k2[2] = t1v.x; k2[3] = t1v.y;
#pragma unroll
            for (int j = 0; j < 4; j++) {
                sA[j] = fma2(qa2, k2[j], sA[j]);
                sB[j] = fma2(qb2, k2[j], sB[j]);
            }
        }
#pragma unroll
        for (int j = 0; j < 4; j++) {
            float a0, a1, b0, b1;
            up2(sA[j], a0, a1);
            up2(sB[j], b0, b1);
            const float pa0 = __expf(a0), pa1 = __expf(a1);
            const float pb0 = __expf(b0), pb1 = __expf(b1);
            lp0 += pa0 + pa1; lp1 += pb0 + pb1;
            *(float2*)&St[(sb+2*j)*132   + sa] = make_float2(pa0, pb0);
            *(float2*)&St[(sb+2*j+1)*132 + sa] = make_float2(pa1, pb1);
        }
        __syncthreads();

        // ---- O += P V  (packed f32x2 over output columns) ----
        for (int j = 0; j < 32; j++) {
            float p8[8];
            *(float4*)&p8[0] = *(float4*)&St[j*132 + r0];
            *(float4*)&p8[4] = *(float4*)&St[j*132 + r0 + 4];
            const ulonglong2* vp = (const ulonglong2*)&Vs[j*132 + c0v];
            const ulonglong2 t0v = vp[0], t1v = vp[1];
            u64 v2[4]; v2[0] = t0v.x; v2[1] = t0v.y; v2[2] = t1v.x; v2[3] = t1v.y;
#pragma unroll
            for (int i = 0; i < 8; i++) {
                const u64 p2 = pk2(p8[i], p8[i]);
#pragma unroll
                for (int jj = 0; jj < 4; jj++) acc2[i][jj] = fma2(p2, v2[jj], acc2[i][jj]);
            }
        }
        __syncthreads();
    }

    // ---- reduce l partials (deterministic) ----
    Lp[sa][hcol]   = lp0;
    Lp[sa+1][hcol] = lp1;
    __syncthreads();
    if (tid < 128)
        lrow[tid] = ((Lp[tid][0] + Lp[tid][1]) + (Lp[tid][2] + Lp[tid][3]));
    __syncthreads();

    // ---- epilogue (packed stores) ----
    float* Ob = Out + ((size_t)bh*QL + q0)*DD;
#pragma unroll
    for (int i = 0; i < 8; i++) {
        const float inv = 1.f/lrow[r0+i];
        const u64 inv2 = pk2(inv, inv);
        ulonglong2 o0, o1;
        o0.x = mul2(inv2, acc2[i][0]); o0.y = mul2(inv2, acc2[i][1]);
        o1.x = mul2(inv2, acc2[i][2]); o1.y = mul2(inv2, acc2[i][3]);
        ((ulonglong2*)&Ob[(r0+i)*DD + c0v])[0] = o0;
        ((ulonglong2*)&Ob[(r0+i)*DD + c0v])[1] = o1;
    }
}

// =========================================================================
extern "C" void kernel_launch(void* const* d_in, const int* in_sizes, int n_in,
                              void* d_out, int out_size)
{
    const float* Q = (const float*)d_in[0];
    const float* K = (const float*)d_in[1];
    const float* V = (const float*)d_in[2];
    float* Out = (float*)d_out;

    const int jac_smem  = DD*PITCH*(int)sizeof(float);          // 66048 B per CTA
    const int proj_smem = (128*XP + 128*RR)*(int)sizeof(float); // 83968 B
    const int attn_smem = (128*33 + 32*36 + 32*132 + 32*132)*(int)sizeof(float); // 55296 B
    cudaFuncSetAttribute(jacobi_cluster_kernel,
                         cudaFuncAttributeMaxDynamicSharedMemorySize, jac_smem);
    cudaFuncSetAttribute(proj_kernel,
                         cudaFuncAttributeMaxDynamicSharedMemorySize, proj_smem);
    cudaFuncSetAttribute(attn_kernel,
                         cudaFuncAttributeMaxDynamicSharedMemorySize, attn_smem);

    gram_partial_kernel<<<dim3(BH, NCH), 256>>>(K);
    jacobi_cluster_kernel<<<2*BH, 1024, jac_smem>>>();
    proj_kernel<<<dim3(BH, KL/128), 256, proj_smem>>>(K, 0);
    proj_kernel<<<dim3(BH, QL/128), 256, proj_smem>>>(Q, 1);
    attn_kernel<<<dim3(BH, QL/128), 256, attn_smem>>>(V, Out);
}

// round 13
// speedup vs baseline: 1.3558x; 1.3168x over previous
#include <cuda_runtime.h>
#include <math.h>
#include <stdint.h>

#define BH 64
#define QL 512
#define KL 4096
#define DD 128
#define RR 32
#define NCH 8
#define CHUNK 512          // KL / NCH
#define MAXSWEEP 8
#define PITCH 129          // smem pitch for 128x128 matrices

typedef unsigned long long u64;

// ---------------- packed f32x2 helpers (sm_103a) ----------------
__device__ __forceinline__ u64 pk2(float x, float y) {
    u64 r; asm("mov.b64 %0,{%1,%2};" : "=l"(r) : "f"(x), "f"(y)); return r;
}
__device__ __forceinline__ u64 fma2(u64 a, u64 b, u64 c) {
    u64 d; asm("fma.rn.f32x2 %0,%1,%2,%3;" : "=l"(d) : "l"(a), "l"(b), "l"(c)); return d;
}
__device__ __forceinline__ u64 mul2(u64 a, u64 b) {
    u64 d; asm("mul.rn.f32x2 %0,%1,%2;" : "=l"(d) : "l"(a), "l"(b)); return d;
}

// ---------------- device scratch (static allocation only) ----------------
__device__ float g_Gpart[BH*NCH*DD*DD];   // partial Gram matrices
__device__ float g_mspart[BH*NCH*DD];     // partial column sums
__device__ float g_B[BH*DD*RR];           // top-32 eigenbasis  [bh][d][r]
__device__ float g_Kp[(size_t)BH*KL*RR];  // K projected
__device__ float g_Qp[(size_t)BH*QL*RR];  // Q projected (pre-scaled)

// ---------------- cluster / mbarrier helpers ----------------
__device__ __forceinline__ uint32_t s2u(const void* p) {
    uint32_t a;
    asm("{ .reg .u64 t; cvta.to.shared.u64 t, %1; cvt.u32.u64 %0, t; }"
        : "=r"(a) : "l"(p));
    return a;
}
__device__ __forceinline__ uint32_t ctarank() {
    uint32_t r; asm("mov.u32 %0, %%cluster_ctarank;" : "=r"(r)); return r;
}
__device__ __forceinline__ uint32_t mapa_u32(uint32_t a, uint32_t r) {
    uint32_t o; asm("mapa.shared::cluster.u32 %0, %1, %2;" : "=r"(o) : "r"(a), "r"(r));
    return o;
}
__device__ __forceinline__ void mbar_init(uint32_t a, uint32_t cnt) {
    asm volatile("mbarrier.init.shared.b64 [%0], %1;" :: "r"(a), "r"(cnt) : "memory");
}
__device__ __forceinline__ void mbar_arrive_remote(uint32_t ra) {
    asm volatile("mbarrier.arrive.release.cluster.shared::cluster.b64 _, [%0];"
                 :: "r"(ra) : "memory");
}
__device__ __forceinline__ void dsmem_st_v2f(uint32_t ra, float x, float y) {
    asm volatile("st.shared::cluster.v2.f32 [%0], {%1,%2};"
                 :: "r"(ra), "f"(x), "f"(y) : "memory");
}
__device__ __forceinline__ void dsmem_st_b32(uint32_t ra, uint32_t v) {
    asm volatile("st.shared::cluster.b32 [%0], %1;" :: "r"(ra), "r"(v) : "memory");
}
// blocking parity wait, cluster-scope acquire
__device__ __forceinline__ void mbar_wait(uint32_t a, uint32_t parity) {
    uint32_t done;
    asm volatile(
        "{\n\t.reg .pred p;\n\t"
        "mbarrier.try_wait.parity.acquire.cluster.shared::cta.b64 p, [%1], %2;\n\t"
        "selp.b32 %0, 1, 0, p;\n\t}"
        : "=r"(done) : "r"(a), "r"(parity) : "memory");
    if (!done) {
        asm volatile(
            "{\n\t.reg .pred P1;\n\t"
            "WL_%=:\n\t"
            "mbarrier.try_wait.parity.acquire.cluster.shared::cta.b64 P1, [%0], %1, 0x989680;\n\t"
            "@P1 bra.uni WD_%=;\n\t"
            "bra.uni WL_%=;\n\t"
            "WD_%=:\n\t}"
            :: "r"(a), "r"(parity) : "memory");
    }
}
#define CLUSTER_SYNC() do { \
    asm volatile("barrier.cluster.arrive.aligned;" ::: "memory"); \
    asm volatile("barrier.cluster.wait.aligned;"   ::: "memory"); \
} while (0)

// =========================================================================
// Kernel 1: partial Gram  G_chunk = K_chunk^T K_chunk   + column sums
// grid (64, 8), 256 threads.  8x8 register tile, f32x2 accumulation.
// =========================================================================
__global__ void gram_partial_kernel(const float* __restrict__ K)
{
    const int bh = blockIdx.x, ch = blockIdx.y;
    const float* Kb = K + ((size_t)bh*KL + (size_t)ch*CHUNK)*DD;

    __shared__ __align__(16) float Ks[16][DD];

    const int tid = threadIdx.x;
    const int ti = tid >> 4, tj = tid & 15;
    u64 acc2[8][4];
#pragma unroll
    for (int i = 0; i < 8; i++)
#pragma unroll
        for (int j = 0; j < 4; j++) acc2[i][j] = 0ull;
    float cs = 0.f;

    for (int n0 = 0; n0 < CHUNK; n0 += 16) {
        const float4* src = (const float4*)(Kb + (size_t)n0*DD);
        float4* dst = (float4*)(&Ks[0][0]);
#pragma unroll
        for (int i = tid; i < 16*DD/4; i += 256) dst[i] = src[i];
        __syncthreads();

        for (int n = 0; n < 16; n++) {
            float a[8];
            *(float4*)&a[0] = *(float4*)&Ks[n][ti*8];
            *(float4*)&a[4] = *(float4*)&Ks[n][ti*8+4];
            u64 b2[4];
            const ulonglong2* bp = (const ulonglong2*)&Ks[n][tj*8];
            ulonglong2 t0 = bp[0], t1 = bp[1];
            b2[0] = t0.x; b2[1] = t0.y; b2[2] = t1.x; b2[3] = t1.y;
#pragma unroll
            for (int i = 0; i < 8; i++) {
                const u64 a2 = pk2(a[i], a[i]);
#pragma unroll
                for (int j = 0; j < 4; j++) acc2[i][j] = fma2(a2, b2[j], acc2[i][j]);
            }
        }
        if (tid < DD) {
#pragma unroll
            for (int n = 0; n < 16; n++) cs += Ks[n][tid];
        }
        __syncthreads();
    }

    float* Gp = g_Gpart + ((size_t)(bh*NCH + ch))*DD*DD;
#pragma unroll
    for (int i = 0; i < 8; i++) {
        ulonglong2* op = (ulonglong2*)&Gp[(ti*8+i)*DD + tj*8];
        ulonglong2 o0, o1;
        o0.x = acc2[i][0]; o0.y = acc2[i][1];
        o1.x = acc2[i][2]; o1.y = acc2[i][3];
        op[0] = o0; op[1] = o1;
    }
    if (tid < DD) g_mspart[(bh*NCH + ch)*DD + tid] = cs;
}

// =========================================================================
// Kernel 2: cluster-split Jacobi. 2 CTAs per bh (rank0: A; rank1: V).
// Coefficients rank0 -> rank1 via 4-slot dsmem ring + mbarriers.
// Coeff chain uses the one-divide form t = 2 apq sgn(d)/(|d|+sqrt(d^2+4apq^2)).
// grid 128 (cluster 2), 1024 threads, 66048 B dynamic smem per CTA.
// =========================================================================
__global__ void __launch_bounds__(1024, 1) __cluster_dims__(2, 1, 1)
jacobi_cluster_kernel()
{
    extern __shared__ float sm[];     // rank0: A[128][129]; rank1: Vm[128][129]

    __shared__ float cbuf[4][132];    // slot: 64x(c,s) interleaved, [128]=flag
    __shared__ __align__(8) unsigned long long mbar[8];  // [0..3]=empty, [4..7]=full
    __shared__ float ssum[DD];
    __shared__ int   pr_[64], qr_[64];
    __shared__ float rc_[64], rs_[64];
    __shared__ float red_o[32], red_d[32];
    __shared__ float ev[DD];
    __shared__ int   rank_[DD];
    __shared__ int   s_done;

    const int bh  = blockIdx.x >> 1;
    const int tid = threadIdx.x;
    const int lane = tid & 31, wid = tid >> 5;
    const uint32_t rk = ctarank();

    const uint32_t cbuf_u  = s2u(&cbuf[0][0]);
    const uint32_t empty_u = s2u(&mbar[0]);
    const uint32_t full_u  = s2u(&mbar[4]);

    if (tid == 0) {
        if (rk == 0) { for (int i = 0; i < 4; i++) mbar_init(empty_u + i*8, 1); }
        else         { for (int i = 0; i < 4; i++) mbar_init(full_u  + i*8, 64); }
    }
    __syncthreads();
    CLUSTER_SYNC();

    if (rk == 0) {
        // =============== rank 0: A-side ===============
        float* A = sm;

        if (tid < DD) {
            float t = 0.f;
#pragma unroll
            for (int c = 0; c < NCH; c++) t += g_mspart[(bh*NCH + c)*DD + tid];
            ssum[tid] = t;
        }
        __syncthreads();
        const float invn = 1.f/(float)KL;
        for (int e = tid; e < DD*DD; e += 1024) {
            const int i = e >> 7, j = e & 127;
            float t = 0.f;
#pragma unroll
            for (int c = 0; c < NCH; c++) t += g_Gpart[((size_t)(bh*NCH + c) << 14) + e];
            A[i*PITCH + j] = t - ssum[i]*ssum[j]*invn;
        }
        __syncthreads();

        int iter = 0, tmod = 0, done = 0;
        for (int sweep = 0; sweep < MAXSWEEP && !done; sweep++) {
            for (int step = 0; step < 127; step++) {
                const int s = iter & 3;

                if (tid < 64) {
                    if (iter >= 4)
                        mbar_wait(empty_u + s*8, (uint32_t)((((iter >> 2)) ^ 1) & 1));

                    int p;
                    if (tid == 0) p = 0;
                    else { int r = tid - 1 - tmod; if (r < 0) r += 127; p = 1 + r; }
                    int r2 = 126 - tid - tmod; if (r2 < 0) r2 += 127;
                    const int q = 1 + r2;

                    const float app = A[p*PITCH + p];
                    const float aqq = A[q*PITCH + q];
                    const float apq = A[p*PITCH + q];
                    float c = 1.f, sv = 0.f;
                    if (fabsf(apq) > 1e-10f*(fabsf(app) + fabsf(aqq)) + 1e-35f) {
                        const float d  = aqq - app;
                        const float r  = sqrtf(fmaf(d, d, 4.f*apq*apq));
                        const float sg = (d >= 0.f) ? 1.f : -1.f;
                        const float t  = __fdividef(2.f*apq*sg, fabsf(d) + r);
                        c = rsqrtf(fmaf(t, t, 1.f));
                        sv = t*c;
                    }
                    pr_[tid] = p; qr_[tid] = q; rc_[tid] = c; rs_[tid] = sv;

                    dsmem_st_v2f(mapa_u32(cbuf_u + (uint32_t)(s*132 + 2*tid)*4u, 1u), c, sv);
                    if (tid == 0)
                        dsmem_st_b32(mapa_u32(cbuf_u + (uint32_t)(s*132 + 128)*4u, 1u), 0u);
                    mbar_arrive_remote(mapa_u32(full_u + s*8, 1u));
                }
                __syncthreads();

                for (int it = tid; it < 4096; it += 1024) {
                    const int m = it >> 6, l = it & 63;
                    const int pm = pr_[m], qm = qr_[m], pl = pr_[l], ql = qr_[l];
                    const float cm = rc_[m], smv = rs_[m], cl = rc_[l], sl = rs_[l];
                    const float a00 = A[pm*PITCH + pl], a01 = A[pm*PITCH + ql];
                    const float a10 = A[qm*PITCH + pl], a11 = A[qm*PITCH + ql];
                    const float r00 = cm*a00 - smv*a10, r01 = cm*a01 - smv*a11;
                    const float r10 = smv*a00 + cm*a10, r11 = smv*a01 + cm*a11;
                    A[pm*PITCH + pl] = cl*r00 - sl*r01;
                    A[pm*PITCH + ql] = sl*r00 + cl*r01;
                    A[qm*PITCH + pl] = cl*r10 - sl*r11;
                    A[qm*PITCH + ql] = sl*r10 + cl*r11;
                }
                __syncthreads();

                iter++;
                if (++tmod == 127) tmod = 0;
            }

            float off2 = 0.f, dia2 = 0.f;
            for (int e = tid; e < DD*DD; e += 1024) {
                const int i = e >> 7, j = e & 127;
                const float a = A[i*PITCH + j];
                if (i == j) dia2 += a*a; else off2 += a*a;
            }
#pragma unroll
            for (int o = 16; o > 0; o >>= 1) {
                off2 += __shfl_down_sync(0xffffffff, off2, o);
                dia2 += __shfl_down_sync(0xffffffff, dia2, o);
            }
            if (lane == 0) { red_o[wid] = off2; red_d[wid] = dia2; }
            __syncthreads();
            if (tid == 0) {
                float o = 0.f, d = 0.f;
#pragma unroll
                for (int w = 0; w < 32; w++) { o += red_o[w]; d += red_d[w]; }
                s_done = (o <= 1e-9f*d) ? 1 : 0;
            }
            __syncthreads();
            done = s_done;
            __syncthreads();
        }

        // ---- final packet: rank map + flag=1 ----
        {
            const int s = iter & 3;
            if (tid == 0)
                mbar_wait(empty_u + s*8, (uint32_t)((((iter >> 2)) ^ 1) & 1));
            __syncthreads();

            if (tid < DD) ev[tid] = A[tid*PITCH + tid];
            __syncthreads();
            if (tid < DD) {
                const float e = ev[tid];
                int r_ = 0;
                for (int j = 0; j < DD; j++) {
                    const float ej = ev[j];
                    if (ej > e || (ej == e && j < tid)) r_++;
                }
                rank_[tid] = r_;
            }
            __syncthreads();
            if (tid < 64) {
                dsmem_st_v2f(mapa_u32(cbuf_u + (uint32_t)(s*132 + 2*tid)*4u, 1u),
                             __int_as_float(rank_[2*tid]), __int_as_float(rank_[2*tid+1]));
                if (tid == 0)
                    dsmem_st_b32(mapa_u32(cbuf_u + (uint32_t)(s*132 + 128)*4u, 1u), 1u);
                mbar_arrive_remote(mapa_u32(full_u + s*8, 1u));
            }
        }
    } else {
        // =============== rank 1: V-side ===============
        float* Vm = sm;
        for (int e = tid; e < DD*DD; e += 1024) {
            const int i = e >> 7, j = e & 127;
            Vm[i*PITCH + j] = (i == j) ? 1.f : 0.f;
        }
        __syncthreads();

        // bounded by max packets rank0 can send (MAXSWEEP*127 rotations + final)
        int tm = 0;
        for (int it = 0; it <= MAXSWEEP*127; it++) {
            const int s = it & 3;
            mbar_wait(full_u + s*8, (uint32_t)((it >> 2) & 1));

            const int flag = __float_as_int(cbuf[s][128]);
            if (flag) {
                float* Bb = g_B + (size_t)bh*DD*RR;
                for (int x = tid; x < DD*DD; x += 1024) {
                    const int k = x >> 7, d = x & 127;
                    const int r = __float_as_int(cbuf[s][d]);
                    if (r < RR) Bb[k*RR + r] = Vm[k*PITCH + d];
                }
                break;
            }

            // V <- V J (whole warp on one pair -> conflict-free)
            for (int x = tid; x < 8192; x += 1024) {
                const int l = x >> 7, k = x & 127;
                int pl;
                if (l == 0) pl = 0;
                else { int r = l - 1 - tm; if (r < 0) r += 127; pl = 1 + r; }
                int r2 = 126 - l - tm; if (r2 < 0) r2 += 127;
                const int ql = 1 + r2;
                const float cl = cbuf[s][2*l], sl = cbuf[s][2*l+1];
                const float vp = Vm[k*PITCH + pl], vq = Vm[k*PITCH + ql];
                Vm[k*PITCH + pl] = cl*vp - sl*vq;
                Vm[k*PITCH + ql] = sl*vp + cl*vq;
            }
            __syncthreads();
            if (tid == 0) mbar_arrive_remote(mapa_u32(empty_u + s*8, 0u));
            if (++tm == 127) tm = 0;
        }
    }

    CLUSTER_SYNC();
}

// =========================================================================
// Kernel 3: projection  Y = X * B * scale  ([bh][rows][128] -> [..][32])
// grid (64, nrows/128), 256 threads, 2x8 register tile per thread. (R10)
// =========================================================================
#define XP 132
__global__ void proj_kernel(const float* __restrict__ X, int is_q)
{
    extern __shared__ float psm[];
    float* Xs = psm;                 // [128][XP]
    float* Bs = psm + 128*XP;        // [128][32]

    const int bh = blockIdx.x;
    const int t0 = blockIdx.y*128;
    const int nrows = is_q ? QL : KL;
    const float scale = is_q ? 0.17677669529663687f : 1.0f;  // 1/sqrt(32)
    float* Y = is_q ? g_Qp : g_Kp;

    const int tid = threadIdx.x;
    const float4* Bsrc = (const float4*)(g_B + (size_t)bh*DD*RR);
    for (int i = tid; i < DD*RR/4; i += 256) ((float4*)Bs)[i] = Bsrc[i];

    const float4* Xb = (const float4*)(X + ((size_t)bh*nrows + t0)*DD);
    for (int i = tid; i < 128*DD/4; i += 256) {
        const int r = i >> 5, c = i & 31;
        *(float4*)&Xs[r*XP + c*4] = Xb[i];
    }
    __syncthreads();

    const int row0 = (tid >> 2)*2, c0 = (tid & 3)*8;
    float a0[8], a1[8];
#pragma unroll
    for (int j = 0; j < 8; j++) { a0[j] = 0.f; a1[j] = 0.f; }

    for (int d = 0; d < DD; d++) {
        const float x0 = Xs[row0*XP + d];
        const float x1 = Xs[(row0+1)*XP + d];
        float b[8];
        *(float4*)&b[0] = *(float4*)&Bs[d*RR + c0];
        *(float4*)&b[4] = *(float4*)&Bs[d*RR + c0 + 4];
#pragma unroll
        for (int j = 0; j < 8; j++) { a0[j] += x0*b[j]; a1[j] += x1*b[j]; }
    }
    float* Yb = Y + ((size_t)bh*nrows + t0 + row0)*RR + c0;
    float4 o0, o1;
    o0.x=a0[0]*scale; o0.y=a0[1]*scale; o0.z=a0[2]*scale; o0.w=a0[3]*scale;
    o1.x=a0[4]*scale; o1.y=a0[5]*scale; o1.z=a0[6]*scale; o1.w=a0[7]*scale;
    *(float4*)&Yb[0] = o0; *(float4*)&Yb[4] = o1;
    o0.x=a1[0]*scale; o0.y=a1[1]*scale; o0.z=a1[2]*scale; o0.w=a1[3]*scale;
    o1.x=a1[4]*scale; o1.y=a1[5]*scale; o1.z=a1[6]*scale; o1.w=a1[7]*scale;
    *(float4*)&Yb[RR] = o0; *(float4*)&Yb[RR+4] = o1;
}

// =========================================================================
// Kernel 4: attention  out = softmax(Qp Kp^T) V   (fp32)
// No max subtraction needed: |score| <= 22.6 -> exp/sums safe in fp32.
// TQ=128, 256 threads, TK=32. Scalar S-compute (R10); PV packed f32x2.
// Vs uses staggered layout w(c) = c + 4*(c>>3), pitch 192: PV v-loads hit
// all 8 bank-groups (2 phases, optimal) instead of 4-way conflicts.
// grid (64, 4).
// =========================================================================
#define VSP 192
__global__ void attn_kernel(const float* __restrict__ V, float* __restrict__ Out)
{
    extern __shared__ float asm_[];
    float* Qs  = asm_;                      // [128][33]
    float* Kst = asm_ + 128*33;             // [32][36]  transposed K chunk
    float* Vs  = asm_ + 128*33 + 32*36;     // [32][VSP] staggered V chunk
    float* St  = Vs + 32*VSP;               // [32][132] transposed exp(scores)

    __shared__ float Lp[128][4];
    __shared__ float lrow[128];

    const int bh = blockIdx.x;
    const int q0 = blockIdx.y*128;

    const int tid = threadIdx.x;               // 256 threads
    const int rg = tid >> 4, cg = tid & 15;
    const int r0 = rg*8;                       // O tile rows
    const int c0v = cg*8;                      // O tile cols (logical)
    const int vw  = cg*12;                     // staggered word base = 12*cg
    const int sa = (tid >> 2)*2, sb = (tid & 3)*8;   // S tile: 2x8
    const int hcol = tid & 3;

    const float* Qp = g_Qp + ((size_t)bh*QL + q0)*RR;
    for (int i = tid; i < 128*RR; i += 256) {
        const int r = i >> 5, c = i & 31;
        Qs[r*33 + c] = Qp[i];
    }

    u64 acc2[8][4];
#pragma unroll
    for (int i = 0; i < 8; i++)
#pragma unroll
        for (int j = 0; j < 4; j++) acc2[i][j] = 0ull;
    float lp0 = 0.f, lp1 = 0.f;
    __syncthreads();

    for (int kc = 0; kc < KL/32; kc++) {
        const int k0 = kc*32;
        const float* Kp = g_Kp + ((size_t)bh*KL + k0)*RR;
        for (int i = tid; i < 32*RR; i += 256) {
            const int r = i >> 5, c = i & 31;
            Kst[c*36 + r] = Kp[i];                  // transpose on store
        }
        const float4* Vb = (const float4*)(V + ((size_t)bh*KL + k0)*DD);
        for (int i = tid; i < 32*DD/4; i += 256) {
            const int r = i >> 5, c4 = i & 31;      // c4 = float4 index in row
            // staggered: word(c) = c + 4*(c>>3); c = 4*c4 -> word = 4*c4 + 4*(c4>>1)
            *(float4*)&Vs[r*VSP + 4*c4 + 4*(c4 >> 1)] = Vb[i];
        }
        __syncthreads();

        // ---- S = exp(Qp Kp^T), 2x8 tile (scalar); store transposed ----
        float s0[8], s1[8];
#pragma unroll
        for (int j = 0; j < 8; j++) { s0[j] = 0.f; s1[j] = 0.f; }
        for (int k = 0; k < RR; k++) {
            const float qa = Qs[sa*33 + k], qb = Qs[(sa+1)*33 + k];
            float kv[8];
            *(float4*)&kv[0] = *(float4*)&Kst[k*36 + sb];
            *(float4*)&kv[4] = *(float4*)&Kst[k*36 + sb + 4];
#pragma unroll
            for (int j = 0; j < 8; j++) { s0[j] += qa*kv[j]; s1[j] += qb*kv[j]; }
        }
#pragma unroll
        for (int j = 0; j < 8; j++) {
            const float p0 = __expf(s0[j]);
            const float p1 = __expf(s1[j]);
            lp0 += p0; lp1 += p1;
            *(float2*)&St[(sb+j)*132 + sa] = make_float2(p0, p1);
        }
        __syncthreads();

        // ---- O += P V  (packed f32x2 over output columns) ----
        for (int j = 0; j < 32; j++) {
            float p8[8];
            *(float4*)&p8[0] = *(float4*)&St[j*132 + r0];
            *(float4*)&p8[4] = *(float4*)&St[j*132 + r0 + 4];
            const ulonglong2* vp = (const ulonglong2*)&Vs[j*VSP + vw];
            const ulonglong2 t0v = vp[0], t1v = vp[1];
            u64 v2[4]; v2[0] = t0v.x; v2[1] = t0v.y; v2[2] = t1v.x; v2[3] = t1v.y;
#pragma unroll
            for (int i = 0; i < 8; i++) {
                const u64 p2 = pk2(p8[i], p8[i]);
#pragma unroll
                for (int jj = 0; jj < 4; jj++) acc2[i][jj] = fma2(p2, v2[jj], acc2[i][jj]);
            }
        }
        __syncthreads();
    }

    // ---- reduce l partials (deterministic) ----
    Lp[sa][hcol]   = lp0;
    Lp[sa+1][hcol] = lp1;
    __syncthreads();
    if (tid < 128)
        lrow[tid] = ((Lp[tid][0] + Lp[tid][1]) + (Lp[tid][2] + Lp[tid][3]));
    __syncthreads();

    // ---- epilogue (packed stores) ----
    float* Ob = Out + ((size_t)bh*QL + q0)*DD;
#pragma unroll
    for (int i = 0; i < 8; i++) {
        const float inv = 1.f/lrow[r0+i];
        const u64 inv2 = pk2(inv, inv);
        ulonglong2 o0, o1;
        o0.x = mul2(inv2, acc2[i][0]); o0.y = mul2(inv2, acc2[i][1]);
        o1.x = mul2(inv2, acc2[i][2]); o1.y = mul2(inv2, acc2[i][3]);
        ((ulonglong2*)&Ob[(r0+i)*DD + c0v])[0] = o0;
        ((ulonglong2*)&Ob[(r0+i)*DD + c0v])[1] = o1;
    }
}

// =========================================================================
extern "C" void kernel_launch(void* const* d_in, const int* in_sizes, int n_in,
                              void* d_out, int out_size)
{
    const float* Q = (const float*)d_in[0];
    const float* K = (const float*)d_in[1];
    const float* V = (const float*)d_in[2];
    float* Out = (float*)d_out;

    const int jac_smem  = DD*PITCH*(int)sizeof(float);          // 66048 B per CTA
    const int proj_smem = (128*XP + 128*RR)*(int)sizeof(float); // 83968 B
    const int attn_smem = (128*33 + 32*36 + 32*VSP + 32*132)*(int)sizeof(float); // 62976 B
    cudaFuncSetAttribute(jacobi_cluster_kernel,
                         cudaFuncAttributeMaxDynamicSharedMemorySize, jac_smem);
    cudaFuncSetAttribute(proj_kernel,
                         cudaFuncAttributeMaxDynamicSharedMemorySize, proj_smem);
    cudaFuncSetAttribute(attn_kernel,
                         cudaFuncAttributeMaxDynamicSharedMemorySize, attn_smem);

    gram_partial_kernel<<<dim3(BH, NCH), 256>>>(K);
    jacobi_cluster_kernel<<<2*BH, 1024, jac_smem>>>();
    proj_kernel<<<dim3(BH, KL/128), 256, proj_smem>>>(K, 0);
    proj_kernel<<<dim3(BH, QL/128), 256, proj_smem>>>(Q, 1);
    attn_kernel<<<dim3(BH, QL/128), 256, attn_smem>>>(V, Out);
}